// round 2
// baseline (speedup 1.0000x reference)
#include <cuda_runtime.h>
#include <cstdint>

#define T_MAX   8192
#define DIN     4096
#define DOUT    4096
#define NE      8
#define NR      8
#define NPAIR   28
#define SCALING 2.0f            // 16.0 / r with r=8
#define XW      132             // padded smem row stride (floats, multiple of 4 for float4)

// -------- scratch (device globals; no allocations allowed) --------
__device__ int    g_cnt[NPAIR];
__device__ int    g_list[NPAIR * T_MAX];
__device__ int2   g_eA[T_MAX];
__device__ float2 g_wA[T_MAX];
__device__ float2 g_cB[T_MAX];
__device__ __align__(16) float g_smid[T_MAX * 16];  // per token: s0[8] (expert lo), s1[8] (expert hi)
__device__ float  g_part[64 * 16];                  // per-block partial prob sums (8 A + 8 B)

// -------- helpers --------
__device__ __forceinline__ void ffma2(uint64_t& acc, uint64_t a, uint64_t b) {
    asm("fma.rn.f32x2 %0, %1, %2, %0;" : "+l"(acc) : "l"(a), "l"(b));
}
__device__ __forceinline__ float2 u2f(uint64_t v) {
    float2 f;
    f.x = __uint_as_float((unsigned)(v & 0xffffffffu));
    f.y = __uint_as_float((unsigned)(v >> 32));
    return f;
}

// -------- kernel 0: zero pair counters --------
__global__ void k_zero() {
    if (threadIdx.x < NPAIR) g_cnt[threadIdx.x] = 0;
}

// -------- kernel 1: routing, pair lists, aux partials --------
__global__ void k_route(const float* __restrict__ la, const float* __restrict__ lb, int T) {
    int t = blockIdx.x * 256 + threadIdx.x;
    float pa[8], pb[8];
#pragma unroll
    for (int i = 0; i < 8; i++) { pa[i] = 0.f; pb[i] = 0.f; }

    if (t < T) {
        // ---- A router ----
        float l[8];
        float4 u0 = *(const float4*)(la + (size_t)t * 8);
        float4 u1 = *(const float4*)(la + (size_t)t * 8 + 4);
        l[0]=u0.x; l[1]=u0.y; l[2]=u0.z; l[3]=u0.w;
        l[4]=u1.x; l[5]=u1.y; l[6]=u1.z; l[7]=u1.w;
        int i0 = 0; float v0 = l[0];
#pragma unroll
        for (int i = 1; i < 8; i++) if (l[i] > v0) { v0 = l[i]; i0 = i; }
        int i1 = -1; float v1 = -1e30f;
#pragma unroll
        for (int i = 0; i < 8; i++) if (i != i0 && l[i] > v1) { v1 = l[i]; i1 = i; }
        float e1 = expf(v1 - v0);
        float inv01 = 1.f / (1.f + e1);
        g_eA[t] = make_int2(i0, i1);
        g_wA[t] = make_float2(inv01, e1 * inv01);
        float s = 0.f;
#pragma unroll
        for (int i = 0; i < 8; i++) { pa[i] = expf(l[i] - v0); s += pa[i]; }
        float invs = 1.f / s;
#pragma unroll
        for (int i = 0; i < 8; i++) pa[i] *= invs;

        // ---- B router ----
        float m[8];
        float4 b0 = *(const float4*)(lb + (size_t)t * 8);
        float4 b1 = *(const float4*)(lb + (size_t)t * 8 + 4);
        m[0]=b0.x; m[1]=b0.y; m[2]=b0.z; m[3]=b0.w;
        m[4]=b1.x; m[5]=b1.y; m[6]=b1.z; m[7]=b1.w;
        int j0 = 0; float w0 = m[0];
#pragma unroll
        for (int i = 1; i < 8; i++) if (m[i] > w0) { w0 = m[i]; j0 = i; }
        int j1 = -1; float w1 = -1e30f;
#pragma unroll
        for (int i = 0; i < 8; i++) if (i != j0 && m[i] > w1) { w1 = m[i]; j1 = i; }
        float eb = expf(w1 - w0);
        float invb = 1.f / (1.f + eb);
        float c0 = SCALING * invb;
        float c1 = SCALING * eb * invb;
        s = 0.f;
#pragma unroll
        for (int i = 0; i < 8; i++) { pb[i] = expf(m[i] - w0); s += pb[i]; }
        invs = 1.f / s;
#pragma unroll
        for (int i = 0; i < 8; i++) pb[i] *= invs;

        // sort B pair ascending so s0 <-> lower expert id
        if (j0 > j1) { int tj = j0; j0 = j1; j1 = tj; float tc = c0; c0 = c1; c1 = tc; }
        g_cB[t] = make_float2(c0, c1);
        int pr = 7 * j0 - (j0 * (j0 - 1)) / 2 + (j1 - j0 - 1);
        int pos = atomicAdd(&g_cnt[pr], 1);
        g_list[pr * T_MAX + pos] = t;
    }

    // deterministic block reduction of prob partials
    __shared__ float wred[8][16];
    int lane = threadIdx.x & 31, wid = threadIdx.x >> 5;
#pragma unroll
    for (int j = 0; j < 16; j++) {
        float v = (j < 8) ? pa[j] : pb[j - 8];
#pragma unroll
        for (int o = 16; o > 0; o >>= 1) v += __shfl_down_sync(0xffffffffu, v, o);
        if (lane == 0) wred[wid][j] = v;
    }
    __syncthreads();
    if (threadIdx.x < 16) {
        float acc = 0.f;
#pragma unroll
        for (int w = 0; w < 8; w++) acc += wred[w][threadIdx.x];
        g_part[blockIdx.x * 16 + threadIdx.x] = acc;
    }
}

// -------- kernel 2: phase A (x @ Wa^T sparse top-2 -> scaled s-vectors) --------
// CTA = 64 tokens, 256 threads. Stages all 8 experts' Wa chunk + x chunk in smem.
__global__ void k_phaseA(const float* __restrict__ x, const float* __restrict__ Wa, int T) {
    extern __shared__ float sm[];
    float* x_s  = sm;                   // 64 * XW
    float* wa_s = sm + 64 * XW;         // 64 * XW, row = r*8 + e
    float* amid = sm + 2 * 64 * XW;     // 64 * 16
    __shared__ int2   eA_s[64];
    __shared__ float2 wA_s[64];
    __shared__ float2 cB_s[64];

    int t0  = blockIdx.x * 64;
    int tid = threadIdx.x;
    if (tid < 64) {
        eA_s[tid] = g_eA[t0 + tid];
        wA_s[tid] = g_wA[t0 + tid];
        cB_s[tid] = g_cB[t0 + tid];
    }
    __syncthreads();

    int tokL = tid >> 2, q = tid & 3;
    int k = q >> 1, rbase = (q & 1) * 4;
    int2 ep = eA_s[tokL];
    int e = k ? ep.y : ep.x;
    int rows[4];
#pragma unroll
    for (int j = 0; j < 4; j++) rows[j] = ((rbase + j) * NE + e) * XW;

    uint64_t acc[4] = {0ull, 0ull, 0ull, 0ull};
    const float* xg = x + (size_t)t0 * DIN;

    for (int ch = 0; ch < DIN / 128; ++ch) {
        __syncthreads();
        // cooperative stage: 64 rows x 128 cols for x and Wa (Wa rows permuted to r*8+e)
#pragma unroll
        for (int rep = 0; rep < 8; ++rep) {
            int v = rep * 256 + tid;          // float4 index among 2048
            int row = v >> 5, c4 = v & 31;
            float4 dx = *(const float4*)(xg + (size_t)row * DIN + ch * 128 + c4 * 4);
            *(float4*)(x_s + row * XW + c4 * 4) = dx;
            float4 dw = *(const float4*)(Wa + (size_t)row * DIN + ch * 128 + c4 * 4);
            int prow = (row & 7) * 8 + (row >> 3);
            *(float4*)(wa_s + prow * XW + c4 * 4) = dw;
        }
        __syncthreads();

        const float* xr = x_s + tokL * XW;
#pragma unroll 4
        for (int c4 = 0; c4 < 32; ++c4) {
            uint64_t x01 = *(const uint64_t*)(xr + c4 * 4);
            uint64_t x23 = *(const uint64_t*)(xr + c4 * 4 + 2);
#pragma unroll
            for (int j = 0; j < 4; j++) {
                const float* wr = wa_s + rows[j] + c4 * 4;
                ffma2(acc[j], x01, *(const uint64_t*)wr);
                ffma2(acc[j], x23, *(const uint64_t*)(wr + 2));
            }
        }
    }

#pragma unroll
    for (int j = 0; j < 4; j++) {
        float2 f = u2f(acc[j]);
        amid[tokL * 16 + q * 4 + j] = f.x + f.y;   // [tok][r] = a(e0,r), [tok][8+r] = a(e1,r)
    }
    __syncthreads();

    for (int v = tid; v < 64 * 16; v += 256) {
        int tok = v >> 4, jj = v & 15;
        int kk = jj >> 3, r = jj & 7;
        float2 wA2 = wA_s[tok];
        float2 cB2 = cB_s[tok];
        float mid = wA2.x * amid[tok * 16 + r] + wA2.y * amid[tok * 16 + 8 + r];
        float c = kk ? cB2.y : cB2.x;
        g_smid[(size_t)(t0 + tok) * 16 + jj] = c * mid;
    }
}

// -------- kernel 3: phase B (pair-partitioned, Wb cols in registers) --------
// grid (28 pairs, 16 col-blocks), 128 threads, thread = 2 output cols.
__global__ void k_phaseB(const float* __restrict__ Wb, float* __restrict__ out) {
    int pair = blockIdx.x;
    int cb   = blockIdx.y;
    int tid  = threadIdx.x;

    int lo = 0, rem = pair;
#pragma unroll
    for (int l = 0; l < 7; l++) { int n = 7 - l; if (rem < n) { lo = l; break; } rem -= n; }
    int hi = lo + 1 + rem;

    int count = g_cnt[pair];
    const int* lst = g_list + pair * T_MAX;
    int o0 = cb * 256 + tid * 2;

    // w[col][rp]: rp 0..3 = expert lo r-pairs, rp 4..7 = expert hi r-pairs
    uint64_t w[2][8];
#pragma unroll
    for (int c = 0; c < 2; c++) {
        const float* pl = Wb + ((size_t)lo * DOUT + (o0 + c)) * 8;
        const float* ph = Wb + ((size_t)hi * DOUT + (o0 + c)) * 8;
#pragma unroll
        for (int rp = 0; rp < 4; rp++) {
            w[c][rp]     = *(const uint64_t*)(pl + rp * 2);
            w[c][rp + 4] = *(const uint64_t*)(ph + rp * 2);
        }
    }

    __shared__ __align__(16) float s_s[64 * 16];
    __shared__ int t_s[64];

    for (int base = 0; base < count; base += 64) {
        int n = min(64, count - base);
        __syncthreads();
        if (tid < n) t_s[tid] = lst[base + tid];
        for (int v = tid; v < n * 4; v += 128) {
            int tk = v >> 2, part = v & 3;
            int t = lst[base + tk];
            *(float4*)(s_s + tk * 16 + part * 4) =
                *(const float4*)(g_smid + (size_t)t * 16 + part * 4);
        }
        __syncthreads();

        for (int i = 0; i < n; ++i) {
            const float* sp = s_s + i * 16;
            uint64_t a[2][2] = {{0ull, 0ull}, {0ull, 0ull}};   // [col][even/odd rp] ILP chains
#pragma unroll
            for (int rp = 0; rp < 8; rp++) {
                uint64_t sv = *(const uint64_t*)(sp + rp * 2);
                ffma2(a[0][rp & 1], sv, w[0][rp]);
                ffma2(a[1][rp & 1], sv, w[1][rp]);
            }
            float2 f00 = u2f(a[0][0]), f01 = u2f(a[0][1]);
            float2 f10 = u2f(a[1][0]), f11 = u2f(a[1][1]);
            int t = t_s[i];
            *(float2*)(out + (size_t)t * DOUT + o0) =
                make_float2((f00.x + f00.y) + (f01.x + f01.y),
                            (f10.x + f10.y) + (f11.x + f11.y));
        }
    }
}

// -------- kernel 4: aux losses --------
__global__ void k_aux(float* __restrict__ out2, int T, int nblk) {
    __shared__ float p[16];
    if (threadIdx.x < 16) {
        float s = 0.f;
        for (int b = 0; b < nblk; b++) s += g_part[b * 16 + threadIdx.x];
        p[threadIdx.x] = s / (float)T;
    }
    __syncthreads();
    if (threadIdx.x == 0) {
        float m = 0.f;
#pragma unroll
        for (int i = 0; i < 8; i++) m += p[i];
        m *= 0.125f;
        float v = 0.f;
#pragma unroll
        for (int i = 0; i < 8; i++) { float d = p[i] - m; v += d * d; }
        out2[0] = 8.f * (v / 7.f);

        float m2 = 0.f;
#pragma unroll
        for (int i = 8; i < 16; i++) m2 += p[i];
        m2 *= 0.125f;
        float v2 = 0.f;
#pragma unroll
        for (int i = 8; i < 16; i++) { float d = p[i] - m2; v2 += d * d; }
        out2[1] = 8.f * (v2 / 7.f);
    }
}

// -------- launcher --------
extern "C" void kernel_launch(void* const* d_in, const int* in_sizes, int n_in,
                              void* d_out, int out_size) {
    const float* x  = (const float*)d_in[0];
    const float* la = (const float*)d_in[1];
    const float* lb = (const float*)d_in[2];
    const float* Wa = (const float*)d_in[3];
    const float* Wb = (const float*)d_in[4];
    float* out = (float*)d_out;

    int T = in_sizes[1] / NE;           // 8192
    if (T > T_MAX) return;
    int nblk = (T + 255) / 256;

    size_t smemA = (size_t)(2 * 64 * XW + 64 * 16) * sizeof(float);
    cudaFuncSetAttribute(k_phaseA, cudaFuncAttributeMaxDynamicSharedMemorySize, (int)smemA);

    k_zero<<<1, 32>>>();
    k_route<<<nblk, 256>>>(la, lb, T);
    k_phaseA<<<T / 64, 256, smemA>>>(x, Wa, T);
    dim3 g3(NPAIR, DOUT / 256);
    k_phaseB<<<g3, 128>>>(Wb, out);
    k_aux<<<1, 32>>>(out + (size_t)out_size - 2, T, nblk);
}

// round 3
// speedup vs baseline: 2.5451x; 2.5451x over previous
#include <cuda_runtime.h>
#include <cstdint>

#define T_MAX   8192
#define DIN     4096
#define DOUT    4096
#define NE      8
#define NPAIR   28
#define SCALING 2.0f            // 16.0 / r with r=8
#define TW      4               // tokens per warp in phase A

// -------- scratch (device globals; no allocations allowed) --------
__device__ int    g_cnt[NPAIR];                 // B-pair counts
__device__ int    g_list[NPAIR * T_MAX];        // B-pair token lists
__device__ int    g_cntA[NPAIR];                // A-pair counts
__device__ int    g_listA[NPAIR * T_MAX];       // A-pair token lists
__device__ float2 g_wA[T_MAX];                  // A weights, sorted (lo, hi)
__device__ float2 g_cB[T_MAX];                  // B coeffs (incl. SCALING), sorted
__device__ __align__(16) float g_smid[T_MAX * 16];
__device__ float  g_part[64 * 16];
// paired Wa: g_wa2[(e*4+q)*4096 + c] as u64 = (Wa[e][2q][c], Wa[e][2q+1][c])
__device__ __align__(16) float g_wa2[NE * 4 * DIN * 2];

// -------- helpers --------
__device__ __forceinline__ void ffma2(uint64_t& acc, uint64_t a, uint64_t b) {
    asm("fma.rn.f32x2 %0, %1, %2, %0;" : "+l"(acc) : "l"(a), "l"(b));
}
__device__ __forceinline__ float2 u2f(uint64_t v) {
    float2 f;
    f.x = __uint_as_float((unsigned)(v & 0xffffffffu));
    f.y = __uint_as_float((unsigned)(v >> 32));
    return f;
}
__device__ __forceinline__ uint64_t dup2(float v) {
    uint64_t r; unsigned u = __float_as_uint(v);
    asm("mov.b64 %0, {%1, %2};" : "=l"(r) : "r"(u), "r"(u));
    return r;
}
__device__ __forceinline__ unsigned sw(unsigned off) { return off ^ ((off >> 3) & 0x70u); }

// -------- kernel 0: zero pair counters --------
__global__ void k_zero() {
    if (threadIdx.x < NPAIR) { g_cnt[threadIdx.x] = 0; g_cntA[threadIdx.x] = 0; }
}

// -------- kernel 0b: build paired Wa layout --------
__global__ void k_prep(const float* __restrict__ Wa) {
    int idx = blockIdx.x * 256 + threadIdx.x;      // 32768 tasks: e4q(32) x c4(1024)
    int e4q = idx >> 10, c4 = idx & 1023;
    int e = e4q >> 2, q = e4q & 3;
    float4 a = *(const float4*)(Wa + ((size_t)(e * 8 + 2 * q) * DIN + c4 * 4));
    float4 b = *(const float4*)(Wa + ((size_t)(e * 8 + 2 * q + 1) * DIN + c4 * 4));
    float* dst = g_wa2 + ((size_t)e4q * DIN + c4 * 4) * 2;
    *(float4*)(dst)     = make_float4(a.x, b.x, a.y, b.y);
    *(float4*)(dst + 4) = make_float4(a.z, b.z, a.w, b.w);
}

// -------- kernel 1: routing, pair lists, aux partials --------
__global__ void k_route(const float* __restrict__ la, const float* __restrict__ lb, int T) {
    int t = blockIdx.x * 256 + threadIdx.x;
    float pa[8], pb[8];
#pragma unroll
    for (int i = 0; i < 8; i++) { pa[i] = 0.f; pb[i] = 0.f; }

    if (t < T) {
        // ---- A router ----
        float l[8];
        float4 u0 = *(const float4*)(la + (size_t)t * 8);
        float4 u1 = *(const float4*)(la + (size_t)t * 8 + 4);
        l[0]=u0.x; l[1]=u0.y; l[2]=u0.z; l[3]=u0.w;
        l[4]=u1.x; l[5]=u1.y; l[6]=u1.z; l[7]=u1.w;
        int i0 = 0; float v0 = l[0];
#pragma unroll
        for (int i = 1; i < 8; i++) if (l[i] > v0) { v0 = l[i]; i0 = i; }
        int i1 = -1; float v1 = -1e30f;
#pragma unroll
        for (int i = 0; i < 8; i++) if (i != i0 && l[i] > v1) { v1 = l[i]; i1 = i; }
        float e1 = expf(v1 - v0);
        float inv01 = 1.f / (1.f + e1);
        float wa0 = inv01, wa1 = e1 * inv01;
        float s = 0.f;
#pragma unroll
        for (int i = 0; i < 8; i++) { pa[i] = expf(l[i] - v0); s += pa[i]; }
        float invs = 1.f / s;
#pragma unroll
        for (int i = 0; i < 8; i++) pa[i] *= invs;
        if (i0 > i1) { int ti = i0; i0 = i1; i1 = ti; float tw = wa0; wa0 = wa1; wa1 = tw; }
        g_wA[t] = make_float2(wa0, wa1);
        int prA = 7 * i0 - (i0 * (i0 - 1)) / 2 + (i1 - i0 - 1);
        int posA = atomicAdd(&g_cntA[prA], 1);
        g_listA[prA * T_MAX + posA] = t;

        // ---- B router ----
        float m[8];
        float4 b0 = *(const float4*)(lb + (size_t)t * 8);
        float4 b1 = *(const float4*)(lb + (size_t)t * 8 + 4);
        m[0]=b0.x; m[1]=b0.y; m[2]=b0.z; m[3]=b0.w;
        m[4]=b1.x; m[5]=b1.y; m[6]=b1.z; m[7]=b1.w;
        int j0 = 0; float w0 = m[0];
#pragma unroll
        for (int i = 1; i < 8; i++) if (m[i] > w0) { w0 = m[i]; j0 = i; }
        int j1 = -1; float w1 = -1e30f;
#pragma unroll
        for (int i = 0; i < 8; i++) if (i != j0 && m[i] > w1) { w1 = m[i]; j1 = i; }
        float eb = expf(w1 - w0);
        float invb = 1.f / (1.f + eb);
        float c0 = SCALING * invb;
        float c1 = SCALING * eb * invb;
        s = 0.f;
#pragma unroll
        for (int i = 0; i < 8; i++) { pb[i] = expf(m[i] - w0); s += pb[i]; }
        invs = 1.f / s;
#pragma unroll
        for (int i = 0; i < 8; i++) pb[i] *= invs;
        if (j0 > j1) { int tj = j0; j0 = j1; j1 = tj; float tc = c0; c0 = c1; c1 = tc; }
        g_cB[t] = make_float2(c0, c1);
        int pr = 7 * j0 - (j0 * (j0 - 1)) / 2 + (j1 - j0 - 1);
        int pos = atomicAdd(&g_cnt[pr], 1);
        g_list[pr * T_MAX + pos] = t;
    }

    // deterministic block reduction of prob partials
    __shared__ float wred[8][16];
    int lane = threadIdx.x & 31, wid = threadIdx.x >> 5;
#pragma unroll
    for (int j = 0; j < 16; j++) {
        float v = (j < 8) ? pa[j] : pb[j - 8];
#pragma unroll
        for (int o = 16; o > 0; o >>= 1) v += __shfl_down_sync(0xffffffffu, v, o);
        if (lane == 0) wred[wid][j] = v;
    }
    __syncthreads();
    if (threadIdx.x < 16) {
        float acc = 0.f;
#pragma unroll
        for (int w = 0; w < 8; w++) acc += wred[w][threadIdx.x];
        g_part[blockIdx.x * 16 + threadIdx.x] = acc;
    }
}

// -------- kernel 2: phase A, pair-partitioned register GEMM --------
// grid (28 pairs, 16 tiles), 256 threads (8 warps x TW=4 tokens = 32 tokens/CTA).
// smem: w2_s[8 pr][1024 cols] u64 (swizzled) = 64 KB per K-chunk, 4 chunks.
__global__ __launch_bounds__(256, 2) void k_phaseA(const float* __restrict__ x) {
    int pair = blockIdx.x, tile = blockIdx.y;
    int cnt = g_cntA[pair];
    int tbase = tile * 32;
    if (tbase >= cnt) return;

    int lo = 0, rem = pair;
#pragma unroll
    for (int l = 0; l < 7; l++) { int n = 7 - l; if (rem < n) { lo = l; break; } rem -= n; }
    int hi = lo + 1 + rem;
    int lo4 = lo * 4, hi4 = hi * 4;

    extern __shared__ __align__(16) char smc[];
    unsigned sbase = (unsigned)__cvta_generic_to_shared(smc);

    int tid = threadIdx.x, warp = tid >> 5, lane = tid & 31;

    int tokg[TW]; bool val[TW];
#pragma unroll
    for (int j = 0; j < TW; j++) {
        int ti = tbase + warp * TW + j;
        val[j] = (ti < cnt);
        tokg[j] = val[j] ? g_listA[pair * T_MAX + ti] : 0;
    }

    uint64_t acc[TW][8];
#pragma unroll
    for (int j = 0; j < TW; j++)
#pragma unroll
        for (int p = 0; p < 8; p++) acc[j][p] = 0ull;

    for (int ch = 0; ch < 4; ++ch) {
        __syncthreads();
        // stage 64KB: 4096 float4 tasks, 16 per thread (coalesced, swizzled STS)
#pragma unroll
        for (int k = 0; k < 16; k++) {
            int idx = k * 256 + tid;
            int pr = idx >> 9, cpos = (idx & 511) << 1;   // cols cpos, cpos+1
            int e4q = (pr < 4) ? (lo4 + pr) : (hi4 + pr - 4);
            float4 v = *(const float4*)(g_wa2 + (((size_t)e4q * DIN + ch * 1024 + cpos) << 1));
            unsigned off = sw((unsigned)(pr * 8192 + cpos * 8));
            *(float4*)(smc + off) = v;
        }
        __syncthreads();

        for (int it = 0; it < 8; ++it) {
            int colbase = ch * 1024 + it * 128 + lane * 4;
            float4 xf[TW];
#pragma unroll
            for (int j = 0; j < TW; j++)
                xf[j] = val[j] ? *(const float4*)(x + (size_t)tokg[j] * DIN + colbase)
                               : make_float4(0.f, 0.f, 0.f, 0.f);
            uint64_t dx[TW][4];
#pragma unroll
            for (int j = 0; j < TW; j++) {
                dx[j][0] = dup2(xf[j].x); dx[j][1] = dup2(xf[j].y);
                dx[j][2] = dup2(xf[j].z); dx[j][3] = dup2(xf[j].w);
            }
            unsigned base = (unsigned)(it * 1024 + lane * 32);
#pragma unroll
            for (int pr = 0; pr < 8; ++pr) {
                unsigned o0 = base + pr * 8192;
                unsigned s0 = sw(o0), s1 = sw(o0 + 16);
                uint64_t w0, w1, w2, w3;
                asm("ld.shared.v2.b64 {%0,%1},[%2];" : "=l"(w0), "=l"(w1) : "r"(sbase + s0));
                asm("ld.shared.v2.b64 {%0,%1},[%2];" : "=l"(w2), "=l"(w3) : "r"(sbase + s1));
#pragma unroll
                for (int j = 0; j < TW; j++) {
                    ffma2(acc[j][pr], w0, dx[j][0]);
                    ffma2(acc[j][pr], w1, dx[j][1]);
                    ffma2(acc[j][pr], w2, dx[j][2]);
                    ffma2(acc[j][pr], w3, dx[j][3]);
                }
            }
        }
    }

    // per-token cross-lane reduce + smid write
#pragma unroll
    for (int j = 0; j < TW; j++) {
        if (!val[j]) continue;              // warp-uniform
        float a[16];
#pragma unroll
        for (int p = 0; p < 8; p++) {
            float2 f = u2f(acc[j][p]);
            a[2 * p] = f.x; a[2 * p + 1] = f.y;   // a[0..7]=e_lo r0..7, a[8..15]=e_hi
        }
#pragma unroll
        for (int o = 16; o > 0; o >>= 1)
#pragma unroll
            for (int i = 0; i < 16; i++) a[i] += __shfl_down_sync(0xffffffffu, a[i], o);
        if (lane == 0) {
            int t = tokg[j];
            float2 wA = g_wA[t], cB = g_cB[t];
            float mid[8];
#pragma unroll
            for (int i = 0; i < 8; i++) mid[i] = wA.x * a[i] + wA.y * a[8 + i];
            float* d = g_smid + (size_t)t * 16;
            *(float4*)(d)      = make_float4(cB.x*mid[0], cB.x*mid[1], cB.x*mid[2], cB.x*mid[3]);
            *(float4*)(d + 4)  = make_float4(cB.x*mid[4], cB.x*mid[5], cB.x*mid[6], cB.x*mid[7]);
            *(float4*)(d + 8)  = make_float4(cB.y*mid[0], cB.y*mid[1], cB.y*mid[2], cB.y*mid[3]);
            *(float4*)(d + 12) = make_float4(cB.y*mid[4], cB.y*mid[5], cB.y*mid[6], cB.y*mid[7]);
        }
    }
}

// -------- kernel 3: phase B (pair-partitioned, token-split x4) --------
// grid (28 pairs, 16 col-blocks, 4 token-quarters), 128 threads, thread = 2 cols.
__global__ void k_phaseB(const float* __restrict__ Wb, float* __restrict__ out) {
    int pair = blockIdx.x, cb = blockIdx.y, q = blockIdx.z;
    int tid = threadIdx.x;

    int lo = 0, rem = pair;
#pragma unroll
    for (int l = 0; l < 7; l++) { int n = 7 - l; if (rem < n) { lo = l; break; } rem -= n; }
    int hi = lo + 1 + rem;

    int count = g_cnt[pair];
    int tstart = (count * q) >> 2, tend = (count * (q + 1)) >> 2;
    const int* lst = g_list + pair * T_MAX;
    int o0 = cb * 256 + tid * 2;

    uint64_t w[2][8];
#pragma unroll
    for (int c = 0; c < 2; c++) {
        const float* pl = Wb + ((size_t)lo * DOUT + (o0 + c)) * 8;
        const float* ph = Wb + ((size_t)hi * DOUT + (o0 + c)) * 8;
#pragma unroll
        for (int rp = 0; rp < 4; rp++) {
            w[c][rp]     = *(const uint64_t*)(pl + rp * 2);
            w[c][rp + 4] = *(const uint64_t*)(ph + rp * 2);
        }
    }

    __shared__ __align__(16) float s_s[64 * 16];
    __shared__ int t_s[64];

    for (int base = tstart; base < tend; base += 64) {
        int n = min(64, tend - base);
        __syncthreads();
        if (tid < n) t_s[tid] = lst[base + tid];
        for (int v = tid; v < n * 4; v += 128) {
            int tk = v >> 2, part = v & 3;
            int t = lst[base + tk];
            *(float4*)(s_s + tk * 16 + part * 4) =
                *(const float4*)(g_smid + (size_t)t * 16 + part * 4);
        }
        __syncthreads();

        for (int i = 0; i < n; ++i) {
            const float* sp = s_s + i * 16;
            uint64_t a[2][2] = {{0ull, 0ull}, {0ull, 0ull}};
#pragma unroll
            for (int rp = 0; rp < 8; rp++) {
                uint64_t sv = *(const uint64_t*)(sp + rp * 2);
                ffma2(a[0][rp & 1], sv, w[0][rp]);
                ffma2(a[1][rp & 1], sv, w[1][rp]);
            }
            float2 f00 = u2f(a[0][0]), f01 = u2f(a[0][1]);
            float2 f10 = u2f(a[1][0]), f11 = u2f(a[1][1]);
            int t = t_s[i];
            *(float2*)(out + (size_t)t * DOUT + o0) =
                make_float2((f00.x + f00.y) + (f01.x + f01.y),
                            (f10.x + f10.y) + (f11.x + f11.y));
        }
    }
}

// -------- kernel 4: aux losses --------
__global__ void k_aux(float* __restrict__ out2, int T, int nblk) {
    __shared__ float p[16];
    if (threadIdx.x < 16) {
        float s = 0.f;
        for (int b = 0; b < nblk; b++) s += g_part[b * 16 + threadIdx.x];
        p[threadIdx.x] = s / (float)T;
    }
    __syncthreads();
    if (threadIdx.x == 0) {
        float m = 0.f;
#pragma unroll
        for (int i = 0; i < 8; i++) m += p[i];
        m *= 0.125f;
        float v = 0.f;
#pragma unroll
        for (int i = 0; i < 8; i++) { float d = p[i] - m; v += d * d; }
        out2[0] = 8.f * (v / 7.f);

        float m2 = 0.f;
#pragma unroll
        for (int i = 8; i < 16; i++) m2 += p[i];
        m2 *= 0.125f;
        float v2 = 0.f;
#pragma unroll
        for (int i = 8; i < 16; i++) { float d = p[i] - m2; v2 += d * d; }
        out2[1] = 8.f * (v2 / 7.f);
    }
}

// -------- launcher --------
extern "C" void kernel_launch(void* const* d_in, const int* in_sizes, int n_in,
                              void* d_out, int out_size) {
    const float* x  = (const float*)d_in[0];
    const float* la = (const float*)d_in[1];
    const float* lb = (const float*)d_in[2];
    const float* Wa = (const float*)d_in[3];
    const float* Wb = (const float*)d_in[4];
    float* out = (float*)d_out;

    int T = in_sizes[1] / NE;           // 8192
    if (T > T_MAX) return;
    int nblk = (T + 255) / 256;

    static int smem_set = 0;
    int smemA = 64 * 1024;
    if (!smem_set) {
        cudaFuncSetAttribute(k_phaseA, cudaFuncAttributeMaxDynamicSharedMemorySize, smemA);
        smem_set = 1;
    }

    k_zero<<<1, 32>>>();
    k_prep<<<128, 256>>>(Wa);
    k_route<<<nblk, 256>>>(la, lb, T);
    dim3 gA(NPAIR, 16);
    k_phaseA<<<gA, 256, smemA>>>(x);
    dim3 gB(NPAIR, DOUT / 256, 4);
    k_phaseB<<<gB, 128>>>(Wb, out);
    k_aux<<<1, 32>>>(out + (size_t)out_size - 2, T, nblk);
}